// round 5
// baseline (speedup 1.0000x reference)
#include <cuda_runtime.h>
#include <cstdint>

#define Nn 2048
#define Dd 64
#define Vv 2048
#define TB 64                        // pair tile dim (64x64)
#define NT (Nn / TB)                 // 32 tiles per dim
#define NTILES (NT * (NT + 1) / 2)   // 528 triangle tiles
#define PADK 33                      // float2 row stride (pad) -> conflict-free
#define MAXB 148                     // k_max blocks
#define NTHR 512

// Scratch (no allocations -> __device__ globals). Every slot fully
// overwritten each call (deterministic).
__device__ float g_part[MAXB];                // per-block maxes of map
__device__ float g_psum[NTILES], g_pcnt[NTILES];

// ---------------------------------------------------------------------------
__device__ __forceinline__ unsigned long long f2add(unsigned long long a,
                                                    unsigned long long b) {
    unsigned long long r;
    asm("add.rn.f32x2 %0, %1, %2;" : "=l"(r) : "l"(a), "l"(b));
    return r;
}

__device__ __forceinline__ void cpa4(uint32_t dst, const float* src) {
    asm volatile("cp.async.ca.shared.global [%0], [%1], 4;" :: "r"(dst), "l"(src));
}

// ---------------------------------------------------------------------------
// per-block max over map_dist -> g_part[bid]; also warms L2 with map (16MB)
__global__ __launch_bounds__(1024) void k_max(const float4* __restrict__ m) {
    __shared__ float sred[32];
    float v = 0.0f;
    for (int i = blockIdx.x * 1024 + threadIdx.x; i < (Vv * Vv / 4);
         i += MAXB * 1024) {
        float4 x = m[i];
        v = fmaxf(fmaxf(v, fmaxf(x.x, x.y)), fmaxf(x.z, x.w));
    }
#pragma unroll
    for (int o = 16; o; o >>= 1) v = fmaxf(v, __shfl_xor_sync(0xffffffffu, v, o));
    int lane = threadIdx.x & 31, w = threadIdx.x >> 5;
    if (lane == 0) sred[w] = v;
    __syncthreads();
    if (w == 0) {
        v = sred[lane];
#pragma unroll
        for (int o = 16; o; o >>= 1) v = fmaxf(v, __shfl_xor_sync(0xffffffffu, v, o));
        if (lane == 0) g_part[blockIdx.x] = v;
    }
}

// ---------------------------------------------------------------------------
extern __shared__ unsigned long long smem_raw[];

// 512 threads, 64x64 tile, thread (tx=tid&31, ty=tid>>5) owns rows ty+16r
// (r<4), cols tx+32c (c<2) = 8 pairs. 2 blocks resident/SM -> 8 warps/SMSP.
// tree+map gathers issued via cp.async up front; latency hidden by mainloop.
__global__ __launch_bounds__(NTHR, 2) void k_main(const int* __restrict__ ids,
                                                  const float2* __restrict__ emb,
                                                  const float* __restrict__ tree,
                                                  const float* __restrict__ mapd) {
    int tid = threadIdx.x;
    int t = blockIdx.x, bi = 0;
    while (t >= NT - bi) { t -= NT - bi; bi++; }
    int bj = bi + t;
    int ibase = bi * TB, jbase = bj * TB;
    bool offdiag = (bi != bj);

    unsigned long long* sA = smem_raw;              // [64][PADK] f32x2
    unsigned long long* sB = smem_raw + TB * PADK;  // negated j-tile
    int* sIdI = (int*)(smem_raw + 2 * TB * PADK);
    int* sIdJ = sIdI + TB;
    float* sSc = (float*)(sIdJ + TB);               // broadcast scale
    float* sMT = sSc + 4;                           // [8][512] gathered tree
    float* sMM = sMT + 8 * NTHR;                    // [8][512] gathered map
    __shared__ float sred[32];

    int tx = tid & 31, ty = tid >> 5;

    // ids first (gather addresses need them); warp 15 reduces g_part -> sc
    if (tid < TB) sIdI[tid] = ids[ibase + tid];
    else if (tid < 2 * TB) sIdJ[tid - TB] = ids[jbase + tid - TB];
    if (ty == 15) {
        float v = 0.0f;
        for (int k = tx; k < MAXB; k += 32) v = fmaxf(v, g_part[k]);
#pragma unroll
        for (int o = 16; o; o >>= 1) v = fmaxf(v, __shfl_xor_sync(0xffffffffu, v, o));
        if (tx == 0) sSc[0] = 0.5f / v;
    }
    __syncthreads();

    // issue 16 gathers per thread (8 pairs x {tree, map}), plane-major
    {
        uint32_t dT = (uint32_t)__cvta_generic_to_shared(sMT) + tid * 4u;
        uint32_t dM = (uint32_t)__cvta_generic_to_shared(sMM) + tid * 4u;
#pragma unroll
        for (int r = 0; r < 4; r++) {
            int off0 = sIdI[ty + 16 * r] * Vv;
#pragma unroll
            for (int c = 0; c < 2; c++) {
                int idx = off0 + sIdJ[tx + 32 * c];
                uint32_t po = (uint32_t)(r * 2 + c) * (NTHR * 4u);
                cpa4(dT + po, tree + idx);
                cpa4(dM + po, mapd + idx);
            }
        }
        asm volatile("cp.async.commit_group;");
    }

    // embedding tiles (coalesced; B negated so diff = packed add)
    for (int x = tid; x < TB * 32; x += NTHR) {
        int row = x >> 5, k2 = x & 31;
        float2 a = emb[(ibase + row) * 32 + k2];
        float2 b = emb[(jbase + row) * 32 + k2];
        ((float2*)sA)[row * PADK + k2] = a;
        b.x = -b.x; b.y = -b.y;
        ((float2*)sB)[row * PADK + k2] = b;
    }
    __syncthreads();

    unsigned long long acc[4][2];
#pragma unroll
    for (int r = 0; r < 4; r++)
#pragma unroll
        for (int c = 0; c < 2; c++) acc[r][c] = 0ull;

    const unsigned long long ABSM = 0x7FFFFFFF7FFFFFFFull;
    const unsigned long long* sArow = sA + ty * PADK;
    const unsigned long long* sBrow = sB + tx * PADK;

#pragma unroll 4
    for (int k2 = 0; k2 < 32; k2++) {
        unsigned long long a2[4], b2[2];
#pragma unroll
        for (int r = 0; r < 4; r++) a2[r] = sArow[(16 * r) * PADK + k2];
#pragma unroll
        for (int c = 0; c < 2; c++) b2[c] = sBrow[(32 * c) * PADK + k2];
#pragma unroll
        for (int r = 0; r < 4; r++) {
#pragma unroll
            for (int c = 0; c < 2; c++) {
                unsigned long long d = f2add(a2[r], b2[c]);  // a - b (packed)
                d &= ABSM;                                   // |.| both halves
                acc[r][c] = f2add(acc[r][c], d);
            }
        }
    }

    // gathers landed long ago; each thread reads only slots it wrote
    asm volatile("cp.async.wait_group 0;" ::: "memory");

    float sc = sSc[0];
    float loss = 0.0f, cnt = 0.0f;
    const float inv64 = 1.0f / 64.0f;
#pragma unroll
    for (int r = 0; r < 4; r++) {
        int ir = ty + 16 * r;
        int idi = sIdI[ir];
        int gi = ibase + ir;
#pragma unroll
        for (int c = 0; c < 2; c++) {
            int jc = tx + 32 * c;
            int idj = sIdJ[jc];
            int gj = jbase + jc;
            if ((offdiag || gi < gj) && idi != idj) {
                unsigned long long v = acc[r][c];
                float lo = __uint_as_float((unsigned)v);
                float hi = __uint_as_float((unsigned)(v >> 32));
                float ed = (lo + hi) * inv64;
                int p = (r * 2 + c) * NTHR + tid;
                float metric = fmaf(sc, sMM[p], 0.5f * sMT[p]);
                loss += fabsf(ed - metric);
                cnt += 1.0f;
            }
        }
    }

#pragma unroll
    for (int o = 16; o; o >>= 1) {
        loss += __shfl_xor_sync(0xffffffffu, loss, o);
        cnt  += __shfl_xor_sync(0xffffffffu, cnt, o);
    }
    int lane = tid & 31, w = tid >> 5;
    if (lane == 0) { sred[w] = loss; sred[16 + w] = cnt; }
    __syncthreads();
    if (tid == 0) {
        float L = 0.0f, C = 0.0f;
#pragma unroll
        for (int i = 0; i < 16; i++) { L += sred[i]; C += sred[16 + i]; }
        g_psum[blockIdx.x] = L;   // plain overwrite (deterministic)
        g_pcnt[blockIdx.x] = C;
    }
}

// ---------------------------------------------------------------------------
__global__ __launch_bounds__(NTHR) void k_final(float* out) {
    __shared__ float sred[32];
    int tid = threadIdx.x;
    float L = 0.0f, C = 0.0f;
    for (int i = tid; i < NTILES; i += NTHR) { L += g_psum[i]; C += g_pcnt[i]; }
#pragma unroll
    for (int o = 16; o; o >>= 1) {
        L += __shfl_xor_sync(0xffffffffu, L, o);
        C += __shfl_xor_sync(0xffffffffu, C, o);
    }
    int lane = tid & 31, w = tid >> 5;
    if (lane == 0) { sred[w] = L; sred[16 + w] = C; }
    __syncthreads();
    if (tid == 0) {
        float LL = 0.0f, CC = 0.0f;
#pragma unroll
        for (int i = 0; i < 16; i++) { LL += sred[i]; CC += sred[16 + i]; }
        out[0] = LL / CC;
    }
}

// ---------------------------------------------------------------------------
extern "C" void kernel_launch(void* const* d_in, const int* in_sizes, int n_in,
                              void* d_out, int out_size) {
    const int*   ids  = (const int*)d_in[0];
    const float* emb  = (const float*)d_in[1];
    const float* tree = (const float*)d_in[2];
    const float* mapd = (const float*)d_in[3];
    float* out = (float*)d_out;

    // smem: tiles 2*64*33*8=33792 + ids 512 + sc 16 + gather 2*8*512*4=32768
    const int SMEM_BYTES = 2 * TB * PADK * 8 + 2 * TB * 4 + 16 + 16 * NTHR * 4;
    cudaFuncSetAttribute(k_main, cudaFuncAttributeMaxDynamicSharedMemorySize,
                         SMEM_BYTES);

    k_max<<<MAXB, 1024>>>((const float4*)mapd);
    k_main<<<NTILES, NTHR, SMEM_BYTES>>>(ids, (const float2*)emb, tree, mapd);
    k_final<<<1, NTHR>>>(out);
}